// round 7
// baseline (speedup 1.0000x reference)
#include <cuda_runtime.h>
#include <math.h>

#define BB 32
#define CC 64
#define LL 512
#define VV 8192
#define NTOK_MAX (BB*LL)      /* 16384 */
#define NELEM (BB*CC*LL)      /* 1048576 */
#define TBTOK 32              /* tokens per argmax block */
#define TR 128                /* codebook rows staged per tile */

// packed f32x2 helpers (sm_100+): lanewise IEEE fma on two packed floats
#define FMA_F32X2(d, a, b, c) \
    asm("fma.rn.f32x2 %0, %1, %2, %3;" : "=l"(d) : "l"(a), "l"(b), "l"(c))
#define UNPACK_F32X2(lo, hi, in) \
    asm("mov.b64 {%0, %1}, %2;" : "=r"(lo), "=r"(hi) : "l"(in))

// ---------------- device scratch (no malloc allowed) ----------------
__device__ float g_cbn[VV*CC];            // normalized codebook, 2MB
__device__ float g_frest[NELEM];          // residual, 4MB
__device__ float g_fhat[NELEM];           // reconstruction, 4MB
__device__ float g_rest_tok[NTOK_MAX*CC]; // downsampled+normalized tokens
__device__ int   g_idx[NTOK_MAX];         // selected codes
__device__ float g_pval[NTOK_MAX*64];     // per-vocab-split partial best val
__device__ int   g_pidx[NTOK_MAX*64];     // per-vocab-split partial best idx
__device__ float g_loss;                  // sum of squared err accum

// ---------------- codebook row-normalize (IEEE sqrt/div, fast-math-proof) ----
__global__ void normalize_cb_kernel(const float* __restrict__ ew) {
    int row = blockIdx.x;
    int lane = threadIdx.x;                 // 32 threads, 2 floats each
    float2 v = reinterpret_cast<const float2*>(ew + row*CC)[lane];
    float ss = v.x*v.x + v.y*v.y;
    #pragma unroll
    for (int off = 16; off > 0; off >>= 1)
        ss += __shfl_xor_sync(0xffffffffu, ss, off);
    float den = fmaxf(__fsqrt_rn(ss), 1e-12f);
    float2 o;
    o.x = __fdiv_rn(v.x, den);
    o.y = __fdiv_rn(v.y, den);
    reinterpret_cast<float2*>(g_cbn + row*CC)[lane] = o;
}

// ---------------- init residual / fhat / loss ----------------
__global__ void init_kernel(const float* __restrict__ f) {
    int i = blockIdx.x*256 + threadIdx.x;
    if (i < NELEM) { g_frest[i] = f[i]; g_fhat[i] = 0.f; }
    if (i == 0) g_loss = 0.f;
}

// ---------- fused area-downsample + row-normalize: warp per token ----------
__global__ void ds_norm_kernel(int s, int r, int ntok) {
    int t = blockIdx.x*8 + (threadIdx.x >> 5);
    if (t >= ntok) return;
    int lane = threadIdx.x & 31;
    int b = t / s, p = t - b*s;
    const float* s0 = g_frest + (b*CC + 2*lane)*LL + p*r;
    const float* s1 = s0 + LL;
    float va = 0.f, vb = 0.f;
    for (int j = 0; j < r; ++j) va += s0[j];
    for (int j = 0; j < r; ++j) vb += s1[j];
    float inv = 1.0f / (float)r;            // r power of two -> exact
    va *= inv; vb *= inv;
    float ss = va*va + vb*vb;
    #pragma unroll
    for (int off = 16; off > 0; off >>= 1)
        ss += __shfl_xor_sync(0xffffffffu, ss, off);
    float den = fmaxf(__fsqrt_rn(ss), 1e-12f);
    float2 o;
    o.x = __fdiv_rn(va, den);
    o.y = __fdiv_rn(vb, den);
    reinterpret_cast<float2*>(g_rest_tok)[t*32 + lane] = o;
}

// ---------------- cosine argmax: 32 tokens/block, FFMA2, 256 threads --------
// thread = codebook row (tid&127) of the 128-row tile x 16 tokens of its half
// (g = tid>>7). NO launch_bounds min-blocks: regs may exceed 128 (no spills).
// Packed accumulators (ax,ay),(az,aw): identical sequential fmaf chains and
// (ax+ay)+(az+aw) horizontal as all previously validated rounds.
__global__ void __launch_bounds__(256) argmax_kernel(int ntok, int chunk, int vs) {
    __shared__ __align__(16) float4 s_tok[TBTOK*16];   // 8KB
    __shared__ __align__(16) float4 s_cb[TR*16];       // 32KB swizzled tile
    __shared__ float  sval[8][16];
    __shared__ int    sidx[8][16];

    int tid = threadIdx.x;
    int t0  = blockIdx.x * TBTOK;

    for (int i = tid; i < TBTOK*16; i += 256) {
        int t = i >> 4, j = i & 15;
        int tg = t0 + t;
        s_tok[i] = (tg < ntok)
                 ? reinterpret_cast<const float4*>(g_rest_tok + tg*CC)[j]
                 : make_float4(0.f, 0.f, 0.f, 0.f);
    }

    int itg = tid & 127;        // row within tile
    int g   = tid >> 7;         // token half (16 tokens each)

    float best[16]; int bidx[16];
    #pragma unroll
    for (int t = 0; t < 16; ++t) { best[t] = -1e30f; bidx[t] = 0; }

    int vstart = blockIdx.y * chunk;
    int ntiles = chunk / TR;

    for (int tile = 0; tile < ntiles; ++tile) {
        __syncthreads();
        const float4* src = reinterpret_cast<const float4*>(g_cbn)
                          + (size_t)(vstart + tile*TR) * 16;
        for (int i = tid; i < TR*16; i += 256) {
            int row = i >> 4, j = i & 15;
            s_cb[(row << 4) | (j ^ (row & 15))] = src[i];
        }
        __syncthreads();

        // this thread's codebook row -> 16 packed-pair registers (64 regs)
        ulonglong2 rrp[16];
        const ulonglong2* cb2 = reinterpret_cast<const ulonglong2*>(s_cb);
        #pragma unroll
        for (int j = 0; j < 16; ++j)
            rrp[j] = cb2[(itg << 4) | (j ^ (itg & 15))];
        int v = vstart + tile*TR + itg;

        #pragma unroll
        for (int t = 0; t < 16; ++t) {
            const ulonglong2* tk =
                reinterpret_cast<const ulonglong2*>(s_tok + (g*16 + t)*16);
            unsigned long long a01 = 0ull, a23 = 0ull;   // (ax,ay),(az,aw)
            #pragma unroll
            for (int j = 0; j < 16; ++j) {
                ulonglong2 tv = tk[j];       // warp-uniform broadcast
                FMA_F32X2(a01, rrp[j].x, tv.x, a01);
                FMA_F32X2(a23, rrp[j].y, tv.y, a23);
            }
            unsigned int uax, uay, uaz, uaw;
            UNPACK_F32X2(uax, uay, a01);
            UNPACK_F32X2(uaz, uaw, a23);
            float d = (__uint_as_float(uax) + __uint_as_float(uay))
                    + (__uint_as_float(uaz) + __uint_as_float(uaw));
            if (d > best[t]) { best[t] = d; bidx[t] = v; }   // '>' keeps lowest v
        }
    }

    // reduce the 4 warps of each token half
    int lane = tid & 31, warp = tid >> 5;
    #pragma unroll
    for (int t = 0; t < 16; ++t) {
        float bv = best[t]; int bi = bidx[t];
        #pragma unroll
        for (int off = 16; off > 0; off >>= 1) {
            float ov = __shfl_down_sync(0xffffffffu, bv, off);
            int   oi = __shfl_down_sync(0xffffffffu, bi, off);
            if (ov > bv || (ov == bv && oi < bi)) { bv = ov; bi = oi; }
        }
        if (lane == 0) { sval[warp][t] = bv; sidx[warp][t] = bi; }
    }
    __syncthreads();
    if (tid < 32) {
        int t = tid & 15, gg = tid >> 4;
        float bv = sval[gg*4][t]; int bi = sidx[gg*4][t];
        #pragma unroll
        for (int w = 1; w < 4; ++w) {
            float ov = sval[gg*4 + w][t]; int oi = sidx[gg*4 + w][t];
            if (ov > bv || (ov == bv && oi < bi)) { bv = ov; bi = oi; }
        }
        int tg = t0 + gg*16 + t;
        if (tg < ntok) {
            if (vs == 1) g_idx[tg] = bi;
            else { g_pval[tg*64 + blockIdx.y] = bv; g_pidx[tg*64 + blockIdx.y] = bi; }
        }
    }
}

// ---------------- reduce vocab splits per token (vs>1 only) ----------------
__global__ void reduce_kernel(int ntok, int vs) {
    int t = blockIdx.x*256 + threadIdx.x;
    if (t >= ntok) return;
    float bv = g_pval[t*64]; int bi = g_pidx[t*64];
    for (int sp = 1; sp < vs; ++sp) {
        float ov = g_pval[t*64 + sp]; int oi = g_pidx[t*64 + sp];
        if (ov > bv || (ov == bv && oi < bi)) { bv = ov; bi = oi; }
    }
    g_idx[t] = bi;
}

// ---------------- fused gather + upsample + Phi conv + residual update + loss ----------------
#define TL 64
#define PHI_SMEM_FLOATS (CC*(TL+2) + CC*193 + CC)
__global__ void __launch_bounds__(256) phi_update_kernel(
    const float* __restrict__ f, const float* __restrict__ ew,
    const float* __restrict__ phiw, const float* __restrict__ phib,
    int s, int pidx, float* __restrict__ outp)
{
    extern __shared__ float sm[];
    float* tile = sm;                 // [64][66]
    float* ws   = sm + CC*(TL+2);     // [64][193]
    float* bs   = ws + CC*193;        // [64]

    int b  = blockIdx.x >> 3;
    int l0 = (blockIdx.x & 7) * TL;
    int tid = threadIdx.x;

    const float* wsrc = phiw + pidx*CC*CC*3;
    for (int i = tid; i < CC*192; i += 256) {
        int co = i / 192, rem = i - co*192;
        ws[co*193 + rem] = wsrc[i];
    }
    if (tid < CC) bs[tid] = phib[pidx*CC + tid];

    for (int i = tid; i < CC*(TL+2); i += 256) {
        int ci = i / (TL+2), j = i - ci*(TL+2);
        int l = l0 + j - 1;
        float v = 0.f;
        if (l >= 0 && l < LL) {
            int tokp = (l * s) >> 9;
            int code = g_idx[b*s + tokp];
            v = ew[code*CC + ci];
        }
        tile[ci*(TL+2) + j] = v;
    }
    __syncthreads();

    int co = tid & 63;
    int pbase = (tid >> 6) * 16;
    float acc[16];
    #pragma unroll
    for (int p = 0; p < 16; ++p) acc[p] = 0.f;

    for (int ci = 0; ci < CC; ++ci) {
        const float* wr = ws + co*193 + ci*3;
        float w0 = wr[0], w1 = wr[1], w2 = wr[2];
        const float* hr = tile + ci*(TL+2) + pbase;
        float h[18];
        #pragma unroll
        for (int j = 0; j < 18; ++j) h[j] = hr[j];
        #pragma unroll
        for (int p = 0; p < 16; ++p)
            acc[p] = fmaf(w0, h[p], fmaf(w1, h[p+1], fmaf(w2, h[p+2], acc[p])));
    }

    float ss = 0.f;
    float bb = bs[co];
    #pragma unroll
    for (int p = 0; p < 16; ++p) {
        int l = l0 + pbase + p;
        float hc = tile[co*(TL+2) + pbase + p + 1];
        float y = 0.5f*hc + 0.5f*(acc[p] + bb);
        int gi = (b*CC + co)*LL + l;
        float fh = g_fhat[gi] + y;
        if (outp) {
            outp[gi] = fh;                 // last scale: write output directly
        } else {
            g_fhat[gi] = fh;
            g_frest[gi] -= y;
        }
        float d = fh - f[gi];
        ss = fmaf(d, d, ss);
    }

    #pragma unroll
    for (int off = 16; off > 0; off >>= 1)
        ss += __shfl_xor_sync(0xffffffffu, ss, off);
    __shared__ float red[8];
    int lane = tid & 31, warp = tid >> 5;
    if (lane == 0) red[warp] = ss;
    __syncthreads();
    if (tid == 0) {
        float tot = 0.f;
        #pragma unroll
        for (int w = 0; w < 8; ++w) tot += red[w];
        atomicAdd(&g_loss, tot);
    }
}

// ---------------- tail: loss scalar (+ zero any padding) ----------------
__global__ void loss_kernel(float* __restrict__ out, int out_size) {
    int i = NELEM + blockIdx.x*256 + threadIdx.x;
    if (i >= out_size) return;
    out[i] = (i == NELEM) ? g_loss * (1.25f / (10.0f * (float)NELEM)) : 0.f;
}

// ---------------- launch ----------------
extern "C" void kernel_launch(void* const* d_in, const int* in_sizes, int n_in,
                              void* d_out, int out_size) {
    // Bind inputs BY ELEMENT COUNT (pairwise distinct -> ordering-immune)
    const float* f    = nullptr;
    const float* ew   = nullptr;
    const float* phiw = nullptr;
    const float* phib = nullptr;
    for (int i = 0; i < n_in; ++i) {
        switch (in_sizes[i]) {
            case 1048576: f    = (const float*)d_in[i]; break;
            case 524288:  ew   = (const float*)d_in[i]; break;
            case 49152:   phiw = (const float*)d_in[i]; break;
            case 256:     phib = (const float*)d_in[i]; break;
            default: break;
        }
    }
    float* out = (float*)d_out;

    const int seg[10] = {1,2,4,8,16,32,64,128,256,512};

    // pmap: bit-exact float64 replication of np.linspace + np.argmin(first-wins)
    int pmap[10];
    {
        double start = 1.0 / 12.0;
        double stop  = 1.0 - 1.0 / 12.0;
        double delta = stop - start;
        double step  = delta / 3.0;
        double ticks[4];
        for (int i = 0; i < 4; ++i) ticks[i] = (double)i * step + start;
        ticks[3] = stop;
        for (int si = 0; si < 10; ++si) {
            double x = (double)si / 9.0;
            int best = 0;
            double bd = fabs(ticks[0] - x);
            for (int i = 1; i < 4; ++i) {
                double d = fabs(ticks[i] - x);
                if (d < bd) { bd = d; best = i; }
            }
            pmap[si] = best;
        }
    }

    cudaFuncSetAttribute(phi_update_kernel,
                         cudaFuncAttributeMaxDynamicSharedMemorySize,
                         PHI_SMEM_FLOATS * (int)sizeof(float));

    normalize_cb_kernel<<<VV, 32>>>(ew);
    init_kernel<<<(NELEM + 255)/256, 256>>>(f);

    for (int si = 0; si < 10; ++si) {
        int s = seg[si];
        int ntok = BB * s;
        int r = LL / s;

        ds_norm_kernel<<<(ntok + 7)/8, 256>>>(s, r, ntok);

        int xblocks = (ntok + TBTOK - 1)/TBTOK;
        int vs = 1;
        while (xblocks * vs < 256 && vs < 64) vs <<= 1;   // pow2, chunk stays /128
        int chunk = VV / vs;
        dim3 agrid(xblocks, vs);
        argmax_kernel<<<agrid, 256>>>(ntok, chunk, vs);

        if (vs > 1)
            reduce_kernel<<<(ntok + 255)/256, 256>>>(ntok, vs);

        phi_update_kernel<<<BB*8, 256, PHI_SMEM_FLOATS*(int)sizeof(float)>>>(
            f, ew, phiw, phib, s, pmap[si], (si == 9) ? out : nullptr);
    }

    loss_kernel<<<(out_size - NELEM + 255)/256, 256>>>(out, out_size);
}

// round 8
// speedup vs baseline: 1.0742x; 1.0742x over previous
#include <cuda_runtime.h>
#include <math.h>

#define BB 32
#define CC 64
#define LL 512
#define VV 8192
#define NTOK_MAX (BB*LL)      /* 16384 */
#define NELEM (BB*CC*LL)      /* 1048576 */
#define TBTOK 64              /* tokens per argmax block */
#define TR 64                 /* codebook rows staged per tile */

// packed f32x2 helpers (sm_100+): lanewise IEEE fma on two packed floats
#define FMA_F32X2(d, a, b, c) \
    asm("fma.rn.f32x2 %0, %1, %2, %3;" : "=l"(d) : "l"(a), "l"(b), "l"(c))
#define UNPACK_F32X2(lo, hi, in) \
    asm("mov.b64 {%0, %1}, %2;" : "=r"(lo), "=r"(hi) : "l"(in))

// ---------------- device scratch (no malloc allowed) ----------------
__device__ float g_cbn[VV*CC];            // normalized codebook, 2MB
__device__ float g_frest[NELEM];          // residual, 4MB
__device__ float g_fhat[NELEM];           // reconstruction, 4MB
__device__ float g_rest_tok[NTOK_MAX*CC]; // downsampled+normalized tokens
__device__ int   g_idx[NTOK_MAX];         // selected codes
__device__ float g_pval[NTOK_MAX*64];     // per-vocab-split partial best val
__device__ int   g_pidx[NTOK_MAX*64];     // per-vocab-split partial best idx
__device__ float g_loss;                  // sum of squared err accum

// ---------------- codebook row-normalize (IEEE sqrt/div, fast-math-proof) ----
__global__ void normalize_cb_kernel(const float* __restrict__ ew) {
    int row = blockIdx.x;
    int lane = threadIdx.x;                 // 32 threads, 2 floats each
    float2 v = reinterpret_cast<const float2*>(ew + row*CC)[lane];
    float ss = v.x*v.x + v.y*v.y;
    #pragma unroll
    for (int off = 16; off > 0; off >>= 1)
        ss += __shfl_xor_sync(0xffffffffu, ss, off);
    float den = fmaxf(__fsqrt_rn(ss), 1e-12f);
    float2 o;
    o.x = __fdiv_rn(v.x, den);
    o.y = __fdiv_rn(v.y, den);
    reinterpret_cast<float2*>(g_cbn + row*CC)[lane] = o;
}

// ---------------- init residual / fhat / loss ----------------
__global__ void init_kernel(const float* __restrict__ f) {
    int i = blockIdx.x*256 + threadIdx.x;
    if (i < NELEM) { g_frest[i] = f[i]; g_fhat[i] = 0.f; }
    if (i == 0) g_loss = 0.f;
}

// ---------- fused area-downsample + row-normalize: warp per token ----------
__global__ void ds_norm_kernel(int s, int r, int ntok) {
    int t = blockIdx.x*8 + (threadIdx.x >> 5);
    if (t >= ntok) return;
    int lane = threadIdx.x & 31;
    int b = t / s, p = t - b*s;
    const float* s0 = g_frest + (b*CC + 2*lane)*LL + p*r;
    const float* s1 = s0 + LL;
    float va = 0.f, vb = 0.f;
    for (int j = 0; j < r; ++j) va += s0[j];
    for (int j = 0; j < r; ++j) vb += s1[j];
    float inv = 1.0f / (float)r;            // r power of two -> exact
    va *= inv; vb *= inv;
    float ss = va*va + vb*vb;
    #pragma unroll
    for (int off = 16; off > 0; off >>= 1)
        ss += __shfl_xor_sync(0xffffffffu, ss, off);
    float den = fmaxf(__fsqrt_rn(ss), 1e-12f);
    float2 o;
    o.x = __fdiv_rn(va, den);
    o.y = __fdiv_rn(vb, den);
    reinterpret_cast<float2*>(g_rest_tok)[t*32 + lane] = o;
}

// ---------------- cosine argmax: 64 tokens/block, FFMA2, 512 threads --------
// thread = row (tid&63) of a 64-row codebook tile x 8 tokens of its group
// (g = tid>>6, 8 groups). ~115 regs -> no spills at the 128 cap, 16 warps/SM.
// Packed accumulators (ax,ay),(az,aw): identical sequential fmaf chains and
// (ax+ay)+(az+aw) horizontal as all previously validated rounds.
__global__ void __launch_bounds__(512) argmax_kernel(int ntok, int chunk, int vs) {
    __shared__ __align__(16) float4 s_tok[TBTOK*16];   // 16KB
    __shared__ __align__(16) float4 s_cb[TR*16];       // 16KB swizzled tile
    __shared__ float  sval[16][8];
    __shared__ int    sidx[16][8];

    int tid = threadIdx.x;
    int t0  = blockIdx.x * TBTOK;

    for (int i = tid; i < TBTOK*16; i += 512) {
        int t = i >> 4, j = i & 15;
        int tg = t0 + t;
        s_tok[i] = (tg < ntok)
                 ? reinterpret_cast<const float4*>(g_rest_tok + tg*CC)[j]
                 : make_float4(0.f, 0.f, 0.f, 0.f);
    }

    int itg = tid & 63;         // row within tile
    int g   = tid >> 6;         // token group (8 tokens each)

    float best[8]; int bidx[8];
    #pragma unroll
    for (int t = 0; t < 8; ++t) { best[t] = -1e30f; bidx[t] = 0; }

    int vstart = blockIdx.y * chunk;
    int ntiles = chunk / TR;

    for (int tile = 0; tile < ntiles; ++tile) {
        __syncthreads();
        const float4* src = reinterpret_cast<const float4*>(g_cbn)
                          + (size_t)(vstart + tile*TR) * 16;
        for (int i = tid; i < TR*16; i += 512) {
            int row = i >> 4, j = i & 15;
            s_cb[(row << 4) | (j ^ (row & 15))] = src[i];
        }
        __syncthreads();

        // this thread's codebook row -> 16 packed-pair registers (64 regs)
        ulonglong2 rrp[16];
        const ulonglong2* cb2 = reinterpret_cast<const ulonglong2*>(s_cb);
        #pragma unroll
        for (int j = 0; j < 16; ++j)
            rrp[j] = cb2[(itg << 4) | (j ^ (itg & 15))];
        int v = vstart + tile*TR + itg;

        #pragma unroll
        for (int t = 0; t < 8; ++t) {
            const ulonglong2* tk =
                reinterpret_cast<const ulonglong2*>(s_tok + (g*8 + t)*16);
            unsigned long long a01 = 0ull, a23 = 0ull;   // (ax,ay),(az,aw)
            #pragma unroll
            for (int j = 0; j < 16; ++j) {
                ulonglong2 tv = tk[j];       // warp-uniform broadcast
                FMA_F32X2(a01, rrp[j].x, tv.x, a01);
                FMA_F32X2(a23, rrp[j].y, tv.y, a23);
            }
            unsigned int uax, uay, uaz, uaw;
            UNPACK_F32X2(uax, uay, a01);
            UNPACK_F32X2(uaz, uaw, a23);
            float d = (__uint_as_float(uax) + __uint_as_float(uay))
                    + (__uint_as_float(uaz) + __uint_as_float(uaw));
            if (d > best[t]) { best[t] = d; bidx[t] = v; }   // '>' keeps lowest v
        }
    }

    // reduce within each warp, then combine the 2 warps of each token group
    int lane = tid & 31, warp = tid >> 5;
    #pragma unroll
    for (int t = 0; t < 8; ++t) {
        float bv = best[t]; int bi = bidx[t];
        #pragma unroll
        for (int off = 16; off > 0; off >>= 1) {
            float ov = __shfl_down_sync(0xffffffffu, bv, off);
            int   oi = __shfl_down_sync(0xffffffffu, bi, off);
            if (ov > bv || (ov == bv && oi < bi)) { bv = ov; bi = oi; }
        }
        if (lane == 0) { sval[warp][t] = bv; sidx[warp][t] = bi; }
    }
    __syncthreads();
    if (tid < 64) {
        int t = tid & 7, gg = tid >> 3;     // 8 groups x 8 tokens
        float bv = sval[gg*2][t];   int bi = sidx[gg*2][t];
        float ov = sval[gg*2+1][t]; int oi = sidx[gg*2+1][t];
        if (ov > bv || (ov == bv && oi < bi)) { bv = ov; bi = oi; }
        int tg = t0 + gg*8 + t;
        if (tg < ntok) {
            if (vs == 1) g_idx[tg] = bi;
            else { g_pval[tg*64 + blockIdx.y] = bv; g_pidx[tg*64 + blockIdx.y] = bi; }
        }
    }
}

// ---------------- reduce vocab splits per token (vs>1 only) ----------------
__global__ void reduce_kernel(int ntok, int vs) {
    int t = blockIdx.x*256 + threadIdx.x;
    if (t >= ntok) return;
    float bv = g_pval[t*64]; int bi = g_pidx[t*64];
    for (int sp = 1; sp < vs; ++sp) {
        float ov = g_pval[t*64 + sp]; int oi = g_pidx[t*64 + sp];
        if (ov > bv || (ov == bv && oi < bi)) { bv = ov; bi = oi; }
    }
    g_idx[t] = bi;
}

// ---------------- fused gather + upsample + Phi conv + residual update + loss ----------------
#define TL 64
#define PHI_SMEM_FLOATS (CC*(TL+2) + CC*193 + CC)
__global__ void __launch_bounds__(256) phi_update_kernel(
    const float* __restrict__ f, const float* __restrict__ ew,
    const float* __restrict__ phiw, const float* __restrict__ phib,
    int s, int pidx, float* __restrict__ outp)
{
    extern __shared__ float sm[];
    float* tile = sm;                 // [64][66]
    float* ws   = sm + CC*(TL+2);     // [64][193]
    float* bs   = ws + CC*193;        // [64]

    int b  = blockIdx.x >> 3;
    int l0 = (blockIdx.x & 7) * TL;
    int tid = threadIdx.x;

    const float* wsrc = phiw + pidx*CC*CC*3;
    for (int i = tid; i < CC*192; i += 256) {
        int co = i / 192, rem = i - co*192;
        ws[co*193 + rem] = wsrc[i];
    }
    if (tid < CC) bs[tid] = phib[pidx*CC + tid];

    for (int i = tid; i < CC*(TL+2); i += 256) {
        int ci = i / (TL+2), j = i - ci*(TL+2);
        int l = l0 + j - 1;
        float v = 0.f;
        if (l >= 0 && l < LL) {
            int tokp = (l * s) >> 9;
            int code = g_idx[b*s + tokp];
            v = ew[code*CC + ci];
        }
        tile[ci*(TL+2) + j] = v;
    }
    __syncthreads();

    int co = tid & 63;
    int pbase = (tid >> 6) * 16;
    float acc[16];
    #pragma unroll
    for (int p = 0; p < 16; ++p) acc[p] = 0.f;

    for (int ci = 0; ci < CC; ++ci) {
        const float* wr = ws + co*193 + ci*3;
        float w0 = wr[0], w1 = wr[1], w2 = wr[2];
        const float* hr = tile + ci*(TL+2) + pbase;
        float h[18];
        #pragma unroll
        for (int j = 0; j < 18; ++j) h[j] = hr[j];
        #pragma unroll
        for (int p = 0; p < 16; ++p)
            acc[p] = fmaf(w0, h[p], fmaf(w1, h[p+1], fmaf(w2, h[p+2], acc[p])));
    }

    float ss = 0.f;
    float bb = bs[co];
    #pragma unroll
    for (int p = 0; p < 16; ++p) {
        int l = l0 + pbase + p;
        float hc = tile[co*(TL+2) + pbase + p + 1];
        float y = 0.5f*hc + 0.5f*(acc[p] + bb);
        int gi = (b*CC + co)*LL + l;
        float fh = g_fhat[gi] + y;
        if (outp) {
            outp[gi] = fh;                 // last scale: write output directly
        } else {
            g_fhat[gi] = fh;
            g_frest[gi] -= y;
        }
        float d = fh - f[gi];
        ss = fmaf(d, d, ss);
    }

    #pragma unroll
    for (int off = 16; off > 0; off >>= 1)
        ss += __shfl_xor_sync(0xffffffffu, ss, off);
    __shared__ float red[8];
    int lane = tid & 31, warp = tid >> 5;
    if (lane == 0) red[warp] = ss;
    __syncthreads();
    if (tid == 0) {
        float tot = 0.f;
        #pragma unroll
        for (int w = 0; w < 8; ++w) tot += red[w];
        atomicAdd(&g_loss, tot);
    }
}

// ---------------- tail: loss scalar (+ zero any padding) ----------------
__global__ void loss_kernel(float* __restrict__ out, int out_size) {
    int i = NELEM + blockIdx.x*256 + threadIdx.x;
    if (i >= out_size) return;
    out[i] = (i == NELEM) ? g_loss * (1.25f / (10.0f * (float)NELEM)) : 0.f;
}

// ---------------- launch ----------------
extern "C" void kernel_launch(void* const* d_in, const int* in_sizes, int n_in,
                              void* d_out, int out_size) {
    // Bind inputs BY ELEMENT COUNT (pairwise distinct -> ordering-immune)
    const float* f    = nullptr;
    const float* ew   = nullptr;
    const float* phiw = nullptr;
    const float* phib = nullptr;
    for (int i = 0; i < n_in; ++i) {
        switch (in_sizes[i]) {
            case 1048576: f    = (const float*)d_in[i]; break;
            case 524288:  ew   = (const float*)d_in[i]; break;
            case 49152:   phiw = (const float*)d_in[i]; break;
            case 256:     phib = (const float*)d_in[i]; break;
            default: break;
        }
    }
    float* out = (float*)d_out;

    const int seg[10] = {1,2,4,8,16,32,64,128,256,512};

    // pmap: bit-exact float64 replication of np.linspace + np.argmin(first-wins)
    int pmap[10];
    {
        double start = 1.0 / 12.0;
        double stop  = 1.0 - 1.0 / 12.0;
        double delta = stop - start;
        double step  = delta / 3.0;
        double ticks[4];
        for (int i = 0; i < 4; ++i) ticks[i] = (double)i * step + start;
        ticks[3] = stop;
        for (int si = 0; si < 10; ++si) {
            double x = (double)si / 9.0;
            int best = 0;
            double bd = fabs(ticks[0] - x);
            for (int i = 1; i < 4; ++i) {
                double d = fabs(ticks[i] - x);
                if (d < bd) { bd = d; best = i; }
            }
            pmap[si] = best;
        }
    }

    cudaFuncSetAttribute(phi_update_kernel,
                         cudaFuncAttributeMaxDynamicSharedMemorySize,
                         PHI_SMEM_FLOATS * (int)sizeof(float));

    normalize_cb_kernel<<<VV, 32>>>(ew);
    init_kernel<<<(NELEM + 255)/256, 256>>>(f);

    for (int si = 0; si < 10; ++si) {
        int s = seg[si];
        int ntok = BB * s;
        int r = LL / s;

        ds_norm_kernel<<<(ntok + 7)/8, 256>>>(s, r, ntok);

        int xblocks = (ntok + TBTOK - 1)/TBTOK;
        int vs = 1;
        while (xblocks * vs < 256 && vs < 64) vs <<= 1;   // pow2; chunk multiple of 64
        int chunk = VV / vs;
        dim3 agrid(xblocks, vs);
        argmax_kernel<<<agrid, 512>>>(ntok, chunk, vs);

        if (vs > 1)
            reduce_kernel<<<(ntok + 255)/256, 256>>>(ntok, vs);

        phi_update_kernel<<<BB*8, 256, PHI_SMEM_FLOATS*(int)sizeof(float)>>>(
            f, ew, phiw, phib, s, pmap[si], (si == 9) ? out : nullptr);
    }

    loss_kernel<<<(out_size - NELEM + 255)/256, 256>>>(out, out_size);
}